// round 1
// baseline (speedup 1.0000x reference)
#include <cuda_runtime.h>
#include <math.h>

// Problem constants
#define BB 2
#define NN 2048
#define CC 512
#define HH 8
#define DH 64
#define WW 64
#define RR 8
#define NG 32            // NN / WW global keys
#define M3 1536          // 3*CC
#define MROWS 4096       // BB*NN
#define LORA_SCALE 0.25f // 2.0/RR

// -------- scratch (device globals; no allocation allowed) --------
__device__ float g_wqkv_eff[CC * M3];   // 3 MB
__device__ float g_wout_eff[CC * CC];   // 1 MB
__device__ float g_qkv[(size_t)MROWS * M3];   // 25 MB
__device__ float g_attn[(size_t)MROWS * CC];  // 8 MB

// ================= effective-weight fold: W_eff = W + A@B * scale ==========
__global__ void eff_qkv_kernel(const float* __restrict__ w,
                               const float* __restrict__ la,
                               const float* __restrict__ lb) {
    int idx = blockIdx.x * blockDim.x + threadIdx.x;
    if (idx >= CC * M3) return;
    int c = idx / M3;
    int n = idx % M3;
    float s = 0.f;
#pragma unroll
    for (int r = 0; r < RR; r++) s += la[c * RR + r] * lb[r * M3 + n];
    g_wqkv_eff[idx] = w[idx] + LORA_SCALE * s;
}

__global__ void eff_out_kernel(const float* __restrict__ w,
                               const float* __restrict__ la,
                               const float* __restrict__ lb) {
    int idx = blockIdx.x * blockDim.x + threadIdx.x;
    if (idx >= CC * CC) return;
    int c = idx / CC;
    int n = idx % CC;
    float s = 0.f;
#pragma unroll
    for (int r = 0; r < RR; r++) s += la[c * RR + r] * lb[r * CC + n];
    g_wout_eff[idx] = w[idx] + LORA_SCALE * s;
}

// ================= classic register-tiled SGEMM (row-major) ================
// C[M,N] = A[M,K] @ B[K,N] (+ bias[N]).  M,N multiples of 128; K multiple of 8.
template <int M, int N, int K, bool HAS_BIAS>
__device__ __forceinline__ void sgemm_body(const float* __restrict__ A,
                                           const float* __restrict__ B,
                                           float* __restrict__ C,
                                           const float* __restrict__ bias) {
    constexpr int BM = 128, BN = 128, BK = 8, TM = 8, TN = 8;
    __shared__ float As[BK][BM];
    __shared__ float Bs[BK][BN];

    const int bx = blockIdx.x;          // column tile
    const int by = blockIdx.y;          // row tile
    const int tid = threadIdx.x;        // 256 threads

    // A tile loads: 128x8 floats -> 1 float4 per thread
    const int aRow = tid >> 1;          // 0..127
    const int aCol = (tid & 1) * 4;     // 0 or 4
    // B tile loads: 8x128 floats -> 1 float4 per thread
    const int bRow = tid >> 5;          // 0..7
    const int bCol = (tid & 31) * 4;    // 0..124

    const int tx = tid & 15;            // 0..15 -> cols tx*8..
    const int ty = tid >> 4;            // 0..15 -> rows ty*8..

    float acc[TM][TN];
#pragma unroll
    for (int i = 0; i < TM; i++)
#pragma unroll
        for (int j = 0; j < TN; j++) acc[i][j] = 0.f;

    const float* Ab = A + (size_t)(by * BM) * K;
    const float* Bb = B + bx * BN;

    for (int k0 = 0; k0 < K; k0 += BK) {
        float4 a4 = *(const float4*)(Ab + (size_t)aRow * K + k0 + aCol);
        As[aCol + 0][aRow] = a4.x;
        As[aCol + 1][aRow] = a4.y;
        As[aCol + 2][aRow] = a4.z;
        As[aCol + 3][aRow] = a4.w;
        float4 b4 = *(const float4*)(Bb + (size_t)(k0 + bRow) * N + bCol);
        *(float4*)&Bs[bRow][bCol] = b4;
        __syncthreads();

#pragma unroll
        for (int kk = 0; kk < BK; kk++) {
            float ar[TM], br[TN];
#pragma unroll
            for (int i = 0; i < TM; i++) ar[i] = As[kk][ty * TM + i];
#pragma unroll
            for (int j = 0; j < TN; j++) br[j] = Bs[kk][tx * TN + j];
#pragma unroll
            for (int i = 0; i < TM; i++)
#pragma unroll
                for (int j = 0; j < TN; j++) acc[i][j] += ar[i] * br[j];
        }
        __syncthreads();
    }

#pragma unroll
    for (int i = 0; i < TM; i++) {
        const int row = by * BM + ty * TM + i;
#pragma unroll
        for (int j = 0; j < TN; j += 4) {
            const int col = bx * BN + tx * TN + j;
            float4 r;
            r.x = acc[i][j + 0];
            r.y = acc[i][j + 1];
            r.z = acc[i][j + 2];
            r.w = acc[i][j + 3];
            if (HAS_BIAS) {
                r.x += bias[col + 0];
                r.y += bias[col + 1];
                r.z += bias[col + 2];
                r.w += bias[col + 3];
            }
            *(float4*)(C + (size_t)row * N + col) = r;
        }
    }
}

__global__ __launch_bounds__(256) void sgemm_qkv_kernel(const float* __restrict__ x) {
    sgemm_body<MROWS, M3, CC, false>(x, g_wqkv_eff, g_qkv, nullptr);
}

__global__ __launch_bounds__(256) void sgemm_out_kernel(float* __restrict__ out,
                                                        const float* __restrict__ bias) {
    sgemm_body<MROWS, CC, CC, true>(g_attn, g_wout_eff, out, bias);
}

// ================= attention: warp per query, d-split across lanes =========
// q,k,v live interleaved in g_qkv: layout [b, n, 3, h, dh], row stride M3.
__global__ __launch_bounds__(128) void attn_kernel() {
    const int warp = threadIdx.x >> 5;
    const int lane = threadIdx.x & 31;
    const int gq = blockIdx.x * 4 + warp;       // 0 .. B*H*N-1
    const int i = gq % NN;
    const int h = (gq / NN) % HH;
    const int b = gq / (NN * HH);

    const float scale = 0.125f;                  // 1/sqrt(64)

    const float* qp = g_qkv + ((size_t)(b * NN + i) * 3 + 0) * CC + h * DH;
    const float q0 = qp[lane] * scale;
    const float q1 = qp[lane + 32] * scale;

    // ---- local causal window: j in [max(0,i-64), i] ----
    float m = -1e30f, l = 0.f, a0 = 0.f, a1 = 0.f;
    const int j0 = (i >= WW) ? i - WW : 0;
    for (int j = j0; j <= i; j++) {
        const float* kp = g_qkv + ((size_t)(b * NN + j) * 3 + 1) * CC + h * DH;
        float s = q0 * kp[lane] + q1 * kp[lane + 32];
        s += __shfl_xor_sync(0xffffffffu, s, 16);
        s += __shfl_xor_sync(0xffffffffu, s, 8);
        s += __shfl_xor_sync(0xffffffffu, s, 4);
        s += __shfl_xor_sync(0xffffffffu, s, 2);
        s += __shfl_xor_sync(0xffffffffu, s, 1);
        const float mn = fmaxf(m, s);
        const float c = __expf(m - mn);
        const float p = __expf(s - mn);
        const float* vp = g_qkv + ((size_t)(b * NN + j) * 3 + 2) * CC + h * DH;
        l = l * c + p;
        a0 = a0 * c + p * vp[lane];
        a1 = a1 * c + p * vp[lane + 32];
        m = mn;
    }
    float o0 = a0 / l;
    float o1 = a1 / l;

    // ---- global strided keys: j = g*64, g=0..31 (no mask) ----
    m = -1e30f; l = 0.f; a0 = 0.f; a1 = 0.f;
#pragma unroll 4
    for (int g = 0; g < NG; g++) {
        const int j = g * WW;
        const float* kp = g_qkv + ((size_t)(b * NN + j) * 3 + 1) * CC + h * DH;
        float s = q0 * kp[lane] + q1 * kp[lane + 32];
        s += __shfl_xor_sync(0xffffffffu, s, 16);
        s += __shfl_xor_sync(0xffffffffu, s, 8);
        s += __shfl_xor_sync(0xffffffffu, s, 4);
        s += __shfl_xor_sync(0xffffffffu, s, 2);
        s += __shfl_xor_sync(0xffffffffu, s, 1);
        const float mn = fmaxf(m, s);
        const float c = __expf(m - mn);
        const float p = __expf(s - mn);
        const float* vp = g_qkv + ((size_t)(b * NN + j) * 3 + 2) * CC + h * DH;
        l = l * c + p;
        a0 = a0 * c + p * vp[lane];
        a1 = a1 * c + p * vp[lane + 32];
        m = mn;
    }
    o0 += a0 / l;
    o1 += a1 / l;

    float* op = g_attn + (size_t)(b * NN + i) * CC + h * DH;
    op[lane] = o0;
    op[lane + 32] = o1;
}

// ================= launch =================================================
extern "C" void kernel_launch(void* const* d_in, const int* in_sizes, int n_in,
                              void* d_out, int out_size) {
    const float* x       = (const float*)d_in[0];
    const float* w_qkv   = (const float*)d_in[1];
    const float* lA_qkv  = (const float*)d_in[2];
    const float* lB_qkv  = (const float*)d_in[3];
    const float* w_out   = (const float*)d_in[4];
    const float* b_out   = (const float*)d_in[5];
    const float* lA_out  = (const float*)d_in[6];
    const float* lB_out  = (const float*)d_in[7];
    float* out = (float*)d_out;

    // 1) fold LoRA into effective weights
    eff_qkv_kernel<<<(CC * M3 + 255) / 256, 256>>>(w_qkv, lA_qkv, lB_qkv);
    eff_out_kernel<<<(CC * CC + 255) / 256, 256>>>(w_out, lA_out, lB_out);

    // 2) qkv = x @ w_qkv_eff   (4096 x 1536 x 512)
    sgemm_qkv_kernel<<<dim3(M3 / 128, MROWS / 128), 256>>>(x);

    // 3) attention (local windowed-causal + global strided), warp per query
    attn_kernel<<<(BB * HH * NN) / 4, 128>>>();

    // 4) out = attn @ w_out_eff + b_out   (4096 x 512 x 512)
    sgemm_out_kernel<<<dim3(CC / 128, MROWS / 128), 256>>>(out, b_out);
}

// round 11
// speedup vs baseline: 1.2354x; 1.2354x over previous
#include <cuda_runtime.h>
#include <math.h>

// Problem constants
#define BB 2
#define NN 2048
#define CC 512
#define HH 8
#define DH 64
#define WW 64
#define RR 8
#define NG 32
#define M3 1536
#define MROWS 4096
#define LORA_SCALE 0.25f

// -------- scratch (device globals; round-1 set, proven clean) --------
__device__ float g_wqkv_eff[CC * M3];   // 3 MB
__device__ float g_wout_eff[CC * CC];   // 1 MB
__device__ float g_qkv[(size_t)MROWS * M3];   // 25 MB
__device__ float g_attn[(size_t)MROWS * CC];  // 8 MB

// ================= effective-weight fold (round-1 verbatim) ===============
__global__ void eff_qkv_kernel(const float* __restrict__ w,
                               const float* __restrict__ la,
                               const float* __restrict__ lb) {
    int idx = blockIdx.x * blockDim.x + threadIdx.x;
    if (idx >= CC * M3) return;
    int c = idx / M3;
    int n = idx % M3;
    float s = 0.f;
#pragma unroll
    for (int r = 0; r < RR; r++) s += la[c * RR + r] * lb[r * M3 + n];
    g_wqkv_eff[idx] = w[idx] + LORA_SCALE * s;
}

__global__ void eff_out_kernel(const float* __restrict__ w,
                               const float* __restrict__ la,
                               const float* __restrict__ lb) {
    int idx = blockIdx.x * blockDim.x + threadIdx.x;
    if (idx >= CC * CC) return;
    int c = idx / CC;
    int n = idx % CC;
    float s = 0.f;
#pragma unroll
    for (int r = 0; r < RR; r++) s += la[c * RR + r] * lb[r * CC + n];
    g_wout_eff[idx] = w[idx] + LORA_SCALE * s;
}

// ================= classic register-tiled SGEMM (round-1 verbatim) ========
// C[M,N] = A[M,K] @ B[K,N] (+ bias[N]).  M,N multiples of 128; K multiple of 8.
template <int M, int N, int K, bool HAS_BIAS>
__device__ __forceinline__ void sgemm_body(const float* __restrict__ A,
                                           const float* __restrict__ B,
                                           float* __restrict__ C,
                                           const float* __restrict__ bias) {
    constexpr int BM = 128, BN = 128, BK = 8, TM = 8, TN = 8;
    __shared__ float As[BK][BM];
    __shared__ float Bs[BK][BN];

    const int bx = blockIdx.x;          // column tile
    const int by = blockIdx.y;          // row tile
    const int tid = threadIdx.x;        // 256 threads

    // A tile loads: 128x8 floats -> 1 float4 per thread
    const int aRow = tid >> 1;          // 0..127
    const int aCol = (tid & 1) * 4;     // 0 or 4
    // B tile loads: 8x128 floats -> 1 float4 per thread
    const int bRow = tid >> 5;          // 0..7
    const int bCol = (tid & 31) * 4;    // 0..124

    const int tx = tid & 15;            // 0..15 -> cols tx*8..
    const int ty = tid >> 4;            // 0..15 -> rows ty*8..

    float acc[TM][TN];
#pragma unroll
    for (int i = 0; i < TM; i++)
#pragma unroll
        for (int j = 0; j < TN; j++) acc[i][j] = 0.f;

    const float* Ab = A + (size_t)(by * BM) * K;
    const float* Bb = B + bx * BN;

    for (int k0 = 0; k0 < K; k0 += BK) {
        float4 a4 = *(const float4*)(Ab + (size_t)aRow * K + k0 + aCol);
        As[aCol + 0][aRow] = a4.x;
        As[aCol + 1][aRow] = a4.y;
        As[aCol + 2][aRow] = a4.z;
        As[aCol + 3][aRow] = a4.w;
        float4 b4 = *(const float4*)(Bb + (size_t)(k0 + bRow) * N + bCol);
        *(float4*)&Bs[bRow][bCol] = b4;
        __syncthreads();

#pragma unroll
        for (int kk = 0; kk < BK; kk++) {
            float ar[TM], br[TN];
#pragma unroll
            for (int i = 0; i < TM; i++) ar[i] = As[kk][ty * TM + i];
#pragma unroll
            for (int j = 0; j < TN; j++) br[j] = Bs[kk][tx * TN + j];
#pragma unroll
            for (int i = 0; i < TM; i++)
#pragma unroll
                for (int j = 0; j < TN; j++) acc[i][j] += ar[i] * br[j];
        }
        __syncthreads();
    }

#pragma unroll
    for (int i = 0; i < TM; i++) {
        const int row = by * BM + ty * TM + i;
#pragma unroll
        for (int j = 0; j < TN; j += 4) {
            const int col = bx * BN + tx * TN + j;
            float4 r;
            r.x = acc[i][j + 0];
            r.y = acc[i][j + 1];
            r.z = acc[i][j + 2];
            r.w = acc[i][j + 3];
            if (HAS_BIAS) {
                r.x += bias[col + 0];
                r.y += bias[col + 1];
                r.z += bias[col + 2];
                r.w += bias[col + 3];
            }
            *(float4*)(C + (size_t)row * N + col) = r;
        }
    }
}

__global__ __launch_bounds__(256) void sgemm_qkv_kernel(const float* __restrict__ x) {
    sgemm_body<MROWS, M3, CC, false>(x, g_wqkv_eff, g_qkv, nullptr);
}

__global__ __launch_bounds__(256) void sgemm_out_kernel(float* __restrict__ out,
                                                        const float* __restrict__ bias) {
    sgemm_body<MROWS, CC, CC, true>(g_attn, g_wout_eff, out, bias);
}

// ================= attention v3: 256 thr, 8 warps x 4 queries, lane=key ===
__device__ __forceinline__ float warp_max(float v) {
    v = fmaxf(v, __shfl_xor_sync(0xffffffffu, v, 16));
    v = fmaxf(v, __shfl_xor_sync(0xffffffffu, v, 8));
    v = fmaxf(v, __shfl_xor_sync(0xffffffffu, v, 4));
    v = fmaxf(v, __shfl_xor_sync(0xffffffffu, v, 2));
    v = fmaxf(v, __shfl_xor_sync(0xffffffffu, v, 1));
    return v;
}
__device__ __forceinline__ float warp_sum(float v) {
    v += __shfl_xor_sync(0xffffffffu, v, 16);
    v += __shfl_xor_sync(0xffffffffu, v, 8);
    v += __shfl_xor_sync(0xffffffffu, v, 4);
    v += __shfl_xor_sync(0xffffffffu, v, 2);
    v += __shfl_xor_sync(0xffffffffu, v, 1);
    return v;
}

__global__ __launch_bounds__(256) void attn3_kernel() {
    __shared__ float4 Qs[32][16];  // plain: reads broadcast
    __shared__ float4 Ks[32][16];  // swizzled: phys c4 = c4 ^ (r&15)
    __shared__ float4 Vs[32][16];  // swizzled

    const int tid = threadIdx.x;
    const int warp = tid >> 5, lane = tid & 31;
    const int qt = blockIdx.x * 32;
    const int h = blockIdx.y, b = blockIdx.z;
    const int q0 = warp * 4;       // 4 queries per warp

    // stage Q (pre-scaled); 512 float4 over 256 threads
    for (int t = tid; t < 512; t += 256) {
        int r = t >> 4, c4 = t & 15;
        float4 v = *((const float4*)(g_qkv + ((size_t)(b * NN + qt + r) * 3 + 0) * CC + h * DH) + c4);
        v.x *= 0.125f; v.y *= 0.125f; v.z *= 0.125f; v.w *= 0.125f;
        Qs[r][c4] = v;
    }

    float m[4], l[4];
    float2 o[4], oL[4];
#pragma unroll
    for (int q = 0; q < 4; q++) {
        m[q] = -1e30f; l[q] = 0.f;
        o[q] = make_float2(0.f, 0.f);
    }

    // ---------------- LOCAL phase ----------------
    const int jt_start = (qt >= 64) ? qt - 64 : 0;
    for (int jt = jt_start; jt <= qt; jt += 32) {
        __syncthreads();
        for (int t = tid; t < 512; t += 256) {
            int r = t >> 4, c4 = t & 15;
            size_t row3 = (size_t)(b * NN + jt + r) * 3;
            int pc = c4 ^ (r & 15);
            Ks[r][pc] = *((const float4*)(g_qkv + (row3 + 1) * CC + h * DH) + c4);
            Vs[r][pc] = *((const float4*)(g_qkv + (row3 + 2) * CC + h * DH) + c4);
        }
        __syncthreads();

        float s[4];
#pragma unroll
        for (int q = 0; q < 4; q++) s[q] = 0.f;
#pragma unroll
        for (int c4 = 0; c4 < 16; c4++) {
            float4 k4 = Ks[lane][c4 ^ (lane & 15)];
#pragma unroll
            for (int q = 0; q < 4; q++) {
                float4 q4 = Qs[q0 + q][c4];
                s[q] += q4.x * k4.x + q4.y * k4.y + q4.z * k4.z + q4.w * k4.w;
            }
        }
        const int j = jt + lane;
        float p[4];
#pragma unroll
        for (int q = 0; q < 4; q++) {
            const int i = qt + q0 + q;
            const bool valid = (j <= i) && (i - j <= WW);
            const float sv = valid ? s[q] : -1e30f;
            const float tmax = warp_max(sv);
            const float mn = fmaxf(m[q], tmax);
            const float corr = __expf(m[q] - mn);
            p[q] = valid ? __expf(s[q] - mn) : 0.f;
            const float ts = warp_sum(p[q]);
            l[q] = l[q] * corr + ts;
            o[q].x *= corr; o[q].y *= corr;
            m[q] = mn;
        }
        const float2* vrows = (const float2*)Vs;
#pragma unroll 8
        for (int jj = 0; jj < 32; jj++) {
            float2 v2 = vrows[jj * 32 + ((((lane >> 1) ^ (jj & 15)) << 1) | (lane & 1))];
#pragma unroll
            for (int q = 0; q < 4; q++) {
                float pj = __shfl_sync(0xffffffffu, p[q], jj);
                o[q].x += pj * v2.x;
                o[q].y += pj * v2.y;
            }
        }
    }
#pragma unroll
    for (int q = 0; q < 4; q++) {
        oL[q].x = o[q].x / l[q];
        oL[q].y = o[q].y / l[q];
        l[q] = 0.f;
        o[q] = make_float2(0.f, 0.f);
    }

    // ---------------- GLOBAL phase (32 strided keys, unmasked) -----------
    __syncthreads();
    for (int t = tid; t < 512; t += 256) {
        int r = t >> 4, c4 = t & 15;
        size_t row3 = (size_t)(b * NN + r * WW) * 3;
        int pc = c4 ^ (r & 15);
        Ks[r][pc] = *((const float4*)(g_qkv + (row3 + 1) * CC + h * DH) + c4);
        Vs[r][pc] = *((const float4*)(g_qkv + (row3 + 2) * CC + h * DH) + c4);
    }
    __syncthreads();
    {
        float s[4];
#pragma unroll
        for (int q = 0; q < 4; q++) s[q] = 0.f;
#pragma unroll
        for (int c4 = 0; c4 < 16; c4++) {
            float4 k4 = Ks[lane][c4 ^ (lane & 15)];
#pragma unroll
            for (int q = 0; q < 4; q++) {
                float4 q4 = Qs[q0 + q][c4];
                s[q] += q4.x * k4.x + q4.y * k4.y + q4.z * k4.z + q4.w * k4.w;
            }
        }
        float p[4];
#pragma unroll
        for (int q = 0; q < 4; q++) {
            const float mn = warp_max(s[q]);
            p[q] = __expf(s[q] - mn);
            l[q] = warp_sum(p[q]);
        }
        const float2* vrows = (const float2*)Vs;
#pragma unroll 8
        for (int jj = 0; jj < 32; jj++) {
            float2 v2 = vrows[jj * 32 + ((((lane >> 1) ^ (jj & 15)) << 1) | (lane & 1))];
#pragma unroll
            for (int q = 0; q < 4; q++) {
                float pj = __shfl_sync(0xffffffffu, p[q], jj);
                o[q].x += pj * v2.x;
                o[q].y += pj * v2.y;
            }
        }
    }

    // out = local + global, store
#pragma unroll
    for (int q = 0; q < 4; q++) {
        const int i = qt + q0 + q;
        float2 r;
        r.x = oL[q].x + o[q].x / l[q];
        r.y = oL[q].y + o[q].y / l[q];
        ((float2*)(g_attn + (size_t)(b * NN + i) * CC + h * DH))[lane] = r;
    }
}

// ================= launch =================================================
extern "C" void kernel_launch(void* const* d_in, const int* in_sizes, int n_in,
                              void* d_out, int out_size) {
    const float* x       = (const float*)d_in[0];
    const float* w_qkv   = (const float*)d_in[1];
    const float* lA_qkv  = (const float*)d_in[2];
    const float* lB_qkv  = (const float*)d_in[3];
    const float* w_out   = (const float*)d_in[4];
    const float* b_out   = (const float*)d_in[5];
    const float* lA_out  = (const float*)d_in[6];
    const float* lB_out  = (const float*)d_in[7];
    float* out = (float*)d_out;

    // 1) fold LoRA into effective weights
    eff_qkv_kernel<<<(CC * M3 + 255) / 256, 256>>>(w_qkv, lA_qkv, lB_qkv);
    eff_out_kernel<<<(CC * CC + 255) / 256, 256>>>(w_out, lA_out, lB_out);

    // 2) qkv = x @ w_qkv_eff   (4096 x 1536 x 512) — round-1 SGEMM
    sgemm_qkv_kernel<<<dim3(M3 / 128, MROWS / 128), 256>>>(x);

    // 3) attention: tiled, 32 queries/block (the ONE changed kernel)
    attn3_kernel<<<dim3(NN / 32, HH, BB), 256>>>();

    // 4) out = attn @ w_out_eff + b_out   (4096 x 512 x 512) — round-1 SGEMM
    sgemm_out_kernel<<<dim3(CC / 128, MROWS / 128), 256>>>(out, b_out);
}

// round 12
// speedup vs baseline: 1.8787x; 1.5206x over previous
#include <cuda_runtime.h>
#include <mma.h>
#include <math.h>

using namespace nvcuda;

// Problem constants
#define BB 2
#define NN 2048
#define CC 512
#define HH 8
#define DH 64
#define WW 64
#define RR 8
#define NG 32
#define M3 1536
#define MROWS 4096
#define LORA_SCALE 0.25f

// -------- scratch (device globals; round-1 set, proven clean) --------
__device__ float g_wqkv_eff[CC * M3];
__device__ float g_wout_eff[CC * CC];
__device__ float g_qkv[(size_t)MROWS * M3];
__device__ float g_attn[(size_t)MROWS * CC];

// ================= effective-weight fold (round-1 verbatim, clean) ========
__global__ void eff_qkv_kernel(const float* __restrict__ w,
                               const float* __restrict__ la,
                               const float* __restrict__ lb) {
    int idx = blockIdx.x * blockDim.x + threadIdx.x;
    if (idx >= CC * M3) return;
    int c = idx / M3;
    int n = idx % M3;
    float s = 0.f;
#pragma unroll
    for (int r = 0; r < RR; r++) s += la[c * RR + r] * lb[r * M3 + n];
    g_wqkv_eff[idx] = w[idx] + LORA_SCALE * s;
}

__global__ void eff_out_kernel(const float* __restrict__ w,
                               const float* __restrict__ la,
                               const float* __restrict__ lb) {
    int idx = blockIdx.x * blockDim.x + threadIdx.x;
    if (idx >= CC * CC) return;
    int c = idx / CC;
    int n = idx % CC;
    float s = 0.f;
#pragma unroll
    for (int r = 0; r < RR; r++) s += la[c * RR + r] * lb[r * CC + n];
    g_wout_eff[idx] = w[idx] + LORA_SCALE * s;
}

// ================= wmma tf32 GEMM body (R6 body; clean linkage pattern) ===
// C[M,N] = A[M,K] @ B[K,N]. Block tile 64x128, 256 thr = 8 warps (2m x 4n),
// warp tile 32x32 via 2x2 wmma 16x16x8 tf32 fragments. Single-buffer smem.
// Structured as template __device__ fn + plain __global__ wrappers — the
// ONLY structure empirically proven to avoid the 128MiB local-pool trip.
template <int N, int K>
__device__ __forceinline__ void wmma_gemm_body(const float* __restrict__ A,
                                               const float* __restrict__ Bm,
                                               float* __restrict__ C) {
    __shared__ __align__(16) float As[64][20];    // ldm 20 (80B, 16B multiple)
    __shared__ __align__(16) float Bs[16][132];   // ldm 132 (528B, 16B multiple)

    const int tid = threadIdx.x;
    const int wid = tid >> 5;
    const int wm = wid >> 2;          // 0..1
    const int wn = wid & 3;           // 0..3
    const int bm = blockIdx.y * 64, bn = blockIdx.x * 128;

    wmma::fragment<wmma::accumulator, 16, 16, 8, float> acc[2][2];
#pragma unroll
    for (int mi = 0; mi < 2; mi++)
#pragma unroll
        for (int ni = 0; ni < 2; ni++) wmma::fill_fragment(acc[mi][ni], 0.f);

    const int ar = tid >> 2, ac4 = tid & 3;       // A: 64 rows x 4 float4
    const int br0 = tid >> 5, bc4 = tid & 31;     // B: rows 0..7 / 8..15

    for (int k0 = 0; k0 < K; k0 += 16) {
        float4 a4 = *(const float4*)(A + (size_t)(bm + ar) * K + k0 + ac4 * 4);
        float4 b0 = *(const float4*)(Bm + (size_t)(k0 + br0) * N + bn + bc4 * 4);
        float4 b1 = *(const float4*)(Bm + (size_t)(k0 + br0 + 8) * N + bn + bc4 * 4);
        __syncthreads();   // previous tile fully consumed by all warps
        As[ar][ac4 * 4 + 0] = wmma::__float_to_tf32(a4.x);
        As[ar][ac4 * 4 + 1] = wmma::__float_to_tf32(a4.y);
        As[ar][ac4 * 4 + 2] = wmma::__float_to_tf32(a4.z);
        As[ar][ac4 * 4 + 3] = wmma::__float_to_tf32(a4.w);
        Bs[br0][bc4 * 4 + 0] = wmma::__float_to_tf32(b0.x);
        Bs[br0][bc4 * 4 + 1] = wmma::__float_to_tf32(b0.y);
        Bs[br0][bc4 * 4 + 2] = wmma::__float_to_tf32(b0.z);
        Bs[br0][bc4 * 4 + 3] = wmma::__float_to_tf32(b0.w);
        Bs[br0 + 8][bc4 * 4 + 0] = wmma::__float_to_tf32(b1.x);
        Bs[br0 + 8][bc4 * 4 + 1] = wmma::__float_to_tf32(b1.y);
        Bs[br0 + 8][bc4 * 4 + 2] = wmma::__float_to_tf32(b1.z);
        Bs[br0 + 8][bc4 * 4 + 3] = wmma::__float_to_tf32(b1.w);
        __syncthreads();

#pragma unroll
        for (int kb = 0; kb < 16; kb += 8) {
            wmma::fragment<wmma::matrix_a, 16, 16, 8, wmma::precision::tf32, wmma::row_major> af[2];
            wmma::fragment<wmma::matrix_b, 16, 16, 8, wmma::precision::tf32, wmma::row_major> bf[2];
#pragma unroll
            for (int mi = 0; mi < 2; mi++)
                wmma::load_matrix_sync(af[mi], &As[wm * 32 + mi * 16][kb], 20);
#pragma unroll
            for (int ni = 0; ni < 2; ni++)
                wmma::load_matrix_sync(bf[ni], &Bs[kb][wn * 32 + ni * 16], 132);
#pragma unroll
            for (int mi = 0; mi < 2; mi++)
#pragma unroll
                for (int ni = 0; ni < 2; ni++)
                    wmma::mma_sync(acc[mi][ni], af[mi], bf[ni], acc[mi][ni]);
        }
    }

#pragma unroll
    for (int mi = 0; mi < 2; mi++)
#pragma unroll
        for (int ni = 0; ni < 2; ni++)
            wmma::store_matrix_sync(C + (size_t)(bm + wm * 32 + mi * 16) * N
                                      + bn + wn * 32 + ni * 16,
                                    acc[mi][ni], N, wmma::mem_row_major);
}

// plain, non-template __global__ wrappers (clean pattern)
__global__ __launch_bounds__(256) void wmma_qkv_kernel(const float* __restrict__ x) {
    wmma_gemm_body<M3, CC>(x, g_wqkv_eff, g_qkv);
}

__global__ __launch_bounds__(256) void wmma_out_kernel(float* __restrict__ out) {
    wmma_gemm_body<CC, CC>(g_attn, g_wout_eff, out);
}

// bias add for the out projection (out += b_out per column)
__global__ void bias_add_kernel(float* __restrict__ out, const float* __restrict__ bias) {
    int idx = blockIdx.x * blockDim.x + threadIdx.x;   // float4 index
    if (idx >= MROWS * CC / 4) return;
    float4 v = ((float4*)out)[idx];
    const float4 bv = ((const float4*)bias)[idx & (CC / 4 - 1)];
    v.x += bv.x; v.y += bv.y; v.z += bv.z; v.w += bv.w;
    ((float4*)out)[idx] = v;
}

// ================= attention v3 (R11 verbatim, proven clean, 70.9us) ======
__device__ __forceinline__ float warp_max(float v) {
    v = fmaxf(v, __shfl_xor_sync(0xffffffffu, v, 16));
    v = fmaxf(v, __shfl_xor_sync(0xffffffffu, v, 8));
    v = fmaxf(v, __shfl_xor_sync(0xffffffffu, v, 4));
    v = fmaxf(v, __shfl_xor_sync(0xffffffffu, v, 2));
    v = fmaxf(v, __shfl_xor_sync(0xffffffffu, v, 1));
    return v;
}
__device__ __forceinline__ float warp_sum(float v) {
    v += __shfl_xor_sync(0xffffffffu, v, 16);
    v += __shfl_xor_sync(0xffffffffu, v, 8);
    v += __shfl_xor_sync(0xffffffffu, v, 4);
    v += __shfl_xor_sync(0xffffffffu, v, 2);
    v += __shfl_xor_sync(0xffffffffu, v, 1);
    return v;
}

__global__ __launch_bounds__(256) void attn3_kernel() {
    __shared__ float4 Qs[32][16];  // plain: reads broadcast
    __shared__ float4 Ks[32][16];  // swizzled: phys c4 = c4 ^ (r&15)
    __shared__ float4 Vs[32][16];  // swizzled

    const int tid = threadIdx.x;
    const int warp = tid >> 5, lane = tid & 31;
    const int qt = blockIdx.x * 32;
    const int h = blockIdx.y, b = blockIdx.z;
    const int q0 = warp * 4;       // 4 queries per warp

    // stage Q (pre-scaled); 512 float4 over 256 threads
    for (int t = tid; t < 512; t += 256) {
        int r = t >> 4, c4 = t & 15;
        float4 v = *((const float4*)(g_qkv + ((size_t)(b * NN + qt + r) * 3 + 0) * CC + h * DH) + c4);
        v.x *= 0.125f; v.y *= 0.125f; v.z *= 0.125f; v.w *= 0.125f;
        Qs[r][c4] = v;
    }

    float m[4], l[4];
    float2 o[4], oL[4];
#pragma unroll
    for (int q = 0; q < 4; q++) {
        m[q] = -1e30f; l[q] = 0.f;
        o[q] = make_float2(0.f, 0.f);
    }

    // ---------------- LOCAL phase ----------------
    const int jt_start = (qt >= 64) ? qt - 64 : 0;
    for (int jt = jt_start; jt <= qt; jt += 32) {
        __syncthreads();
        for (int t = tid; t < 512; t += 256) {
            int r = t >> 4, c4 = t & 15;
            size_t row3 = (size_t)(b * NN + jt + r) * 3;
            int pc = c4 ^ (r & 15);
            Ks[r][pc] = *((const float4*)(g_qkv + (row3 + 1) * CC + h * DH) + c4);
            Vs[r][pc] = *((const float4*)(g_qkv + (row3 + 2) * CC + h * DH) + c4);
        }
        __syncthreads();

        float s[4];
#pragma unroll
        for (int q = 0; q < 4; q++) s[q] = 0.f;
#pragma unroll
        for (int c4 = 0; c4 < 16; c4++) {
            float4 k4 = Ks[lane][c4 ^ (lane & 15)];
#pragma unroll
            for (int q = 0; q < 4; q++) {
                float4 q4 = Qs[q0 + q][c4];
                s[q] += q4.x * k4.x + q4.y * k4.y + q4.z * k4.z + q4.w * k4.w;
            }
        }
        const int j = jt + lane;
        float p[4];
#pragma unroll
        for (int q = 0; q < 4; q++) {
            const int i = qt + q0 + q;
            const bool valid = (j <= i) && (i - j <= WW);
            const float sv = valid ? s[q] : -1e30f;
            const float tmax = warp_max(sv);
            const float mn = fmaxf(m[q], tmax);
            const float corr = __expf(m[q] - mn);
            p[q] = valid ? __expf(s[q] - mn) : 0.f;
            const float ts = warp_sum(p[q]);
            l[q] = l[q] * corr + ts;
            o[q].x *= corr; o[q].y *= corr;
            m[q] = mn;
        }
        const float2* vrows = (const float2*)Vs;
#pragma unroll 8
        for (int jj = 0; jj < 32; jj++) {
            float2 v2 = vrows[jj * 32 + ((((lane >> 1) ^ (jj & 15)) << 1) | (lane & 1))];
#pragma unroll
            for (int q = 0; q < 4; q++) {
                float pj = __shfl_sync(0xffffffffu, p[q], jj);
                o[q].x += pj * v2.x;
                o[q].y += pj * v2.y;
            }
        }
    }
#pragma unroll
    for (int q = 0; q < 4; q++) {
        oL[q].x = o[q].x / l[q];
        oL[q].y = o[q].y / l[q];
        l[q] = 0.f;
        o[q] = make_float2(0.f, 0.f);
    }

    // ---------------- GLOBAL phase (32 strided keys, unmasked) -----------
    __syncthreads();
    for (int t = tid; t < 512; t += 256) {
        int r = t >> 4, c4 = t & 15;
        size_t row3 = (size_t)(b * NN + r * WW) * 3;
        int pc = c4 ^ (r & 15);
        Ks[r][pc] = *((const float4*)(g_qkv + (row3 + 1) * CC + h * DH) + c4);
        Vs[r][pc] = *((const float4*)(g_qkv + (row3 + 2) * CC + h * DH) + c4);
    }
    __syncthreads();
    {
        float s[4];
#pragma unroll
        for (int q = 0; q < 4; q++) s[q] = 0.f;
#pragma unroll
        for (int c4 = 0; c4 < 16; c4++) {
            float4 k4 = Ks[lane][c4 ^ (lane & 15)];
#pragma unroll
            for (int q = 0; q < 4; q++) {
                float4 q4 = Qs[q0 + q][c4];
                s[q] += q4.x * k4.x + q4.y * k4.y + q4.z * k4.z + q4.w * k4.w;
            }
        }
        float p[4];
#pragma unroll
        for (int q = 0; q < 4; q++) {
            const float mn = warp_max(s[q]);
            p[q] = __expf(s[q] - mn);
            l[q] = warp_sum(p[q]);
        }
        const float2* vrows = (const float2*)Vs;
#pragma unroll 8
        for (int jj = 0; jj < 32; jj++) {
            float2 v2 = vrows[jj * 32 + ((((lane >> 1) ^ (jj & 15)) << 1) | (lane & 1))];
#pragma unroll
            for (int q = 0; q < 4; q++) {
                float pj = __shfl_sync(0xffffffffu, p[q], jj);
                o[q].x += pj * v2.x;
                o[q].y += pj * v2.y;
            }
        }
    }

    // out = local + global, store
#pragma unroll
    for (int q = 0; q < 4; q++) {
        const int i = qt + q0 + q;
        float2 r;
        r.x = oL[q].x + o[q].x / l[q];
        r.y = oL[q].y + o[q].y / l[q];
        ((float2*)(g_attn + (size_t)(b * NN + i) * CC + h * DH))[lane] = r;
    }
}

// ================= launch =================================================
extern "C" void kernel_launch(void* const* d_in, const int* in_sizes, int n_in,
                              void* d_out, int out_size) {
    const float* x       = (const float*)d_in[0];
    const float* w_qkv   = (const float*)d_in[1];
    const float* lA_qkv  = (const float*)d_in[2];
    const float* lB_qkv  = (const float*)d_in[3];
    const float* w_out   = (const float*)d_in[4];
    const float* b_out   = (const float*)d_in[5];
    const float* lA_out  = (const float*)d_in[6];
    const float* lB_out  = (const float*)d_in[7];
    float* out = (float*)d_out;

    // 1) fold LoRA into effective weights
    eff_qkv_kernel<<<(CC * M3 + 255) / 256, 256>>>(w_qkv, lA_qkv, lB_qkv);
    eff_out_kernel<<<(CC * CC + 255) / 256, 256>>>(w_out, lA_out, lB_out);

    // 2) qkv = x @ w_qkv_eff : 4096 x 1536 x 512 (wmma tf32)
    wmma_qkv_kernel<<<dim3(M3 / 128, MROWS / 64), 256>>>(x);

    // 3) attention: tiled, 32 queries/block (clean, 70.9us)
    attn3_kernel<<<dim3(NN / 32, HH, BB), 256>>>();

    // 4) out = attn @ w_out_eff + b_out : 4096 x 512 x 512 (wmma tf32)
    wmma_out_kernel<<<dim3(CC / 128, MROWS / 64), 256>>>(out);
    bias_add_kernel<<<(MROWS * CC / 4 + 255) / 256, 256>>>(out, b_out);
}